// round 15
// baseline (speedup 1.0000x reference)
#include <cuda_runtime.h>
#include <cuda_fp16.h>
#include <cstdint>

// Problem constants (fixed by setup_inputs)
#define BWIN   4096
#define NTOK   49
#define CDIM   256
#define NHEAD  8
#define MROWS  (BWIN * NTOK)   // 200704

// ---------------------------------------------------------------------------
// Scratch (device globals; no runtime allocation allowed)
// ---------------------------------------------------------------------------
__device__ __half   g_qkv[(size_t)MROWS * 768];
__device__ uint32_t g_wqkv[6 * 16 * 32 * 32];        // word-major frag fp16 words
__device__ uint32_t g_wproj[2 * 16 * 32 * 32];
__device__ uint32_t g_bias[NHEAD * 64 * 32];         // [h][i][t][8] half2 words

__device__ __forceinline__ uint32_t pack_h2(float a, float b) {
    __half2 h = __floats2half2_rn(a, b);
    return *(uint32_t*)&h;
}

// ---------------------------------------------------------------------------
// Weight conversion: fp32 W[K,N] -> word-major fragment words (coalesced):
//   dst[((nblk*16 + kc)*32 + w)*32 + lane],  w = wq*8 + nt*2 + reg
//   lane = g*4 + t;  n = nblk*128 + wq*32 + nt*8 + g;  k = kc*16 + reg*8 + t*2
// ---------------------------------------------------------------------------
__global__ void convert_w(const float* __restrict__ w, uint32_t* __restrict__ dst, int N)
{
    const int idx  = blockIdx.x * 256 + threadIdx.x;
    const int lane = idx & 31;
    const int wrd  = (idx >> 5) & 31;
    const int kc   = (idx >> 10) & 15;
    const int nblk = idx >> 14;
    const int wq  = wrd >> 3;
    const int nt  = (wrd >> 1) & 3;
    const int reg = wrd & 1;
    const int g = lane >> 2, t = lane & 3;
    const int n = nblk * 128 + wq * 32 + nt * 8 + g;
    const int k = kc * 16 + reg * 8 + t * 2;
    dst[idx] = pack_h2(w[(size_t)k * N + n], w[(size_t)(k + 1) * N + n]);
}

// ---------------------------------------------------------------------------
// Bias+mask table: g_bias[((h*64+i)*4 + t)*8 + nt] = half2(B(i,j), B(i,j+1))
// ---------------------------------------------------------------------------
__global__ void build_bias(const float* __restrict__ rpb, uint32_t* __restrict__ dst)
{
    const int idx = blockIdx.x * 256 + threadIdx.x;
    const int nt = idx & 7;
    const int t  = (idx >> 3) & 3;
    const int i  = (idx >> 5) & 63;
    const int h  = idx >> 11;
    const int j0 = nt * 8 + 2 * t;
    float v[2];
#pragma unroll
    for (int e = 0; e < 2; e++) {
        const int j = j0 + e;
        if (i < NTOK && j < NTOK && nt < 7) {
            const int xi = i / 7, yi = i - xi * 7;
            const int xj = j / 7, yj = j - xj * 7;
            v[e] = rpb[((xi - xj + 6) * 13 + (yi - yj + 6)) * 8 + h];
        } else {
            v[e] = -10000.0f;
        }
    }
    dst[idx] = pack_h2(v[0], v[1]);
}

// ---------------------------------------------------------------------------
// QKV GEMM: barrier-free A-resident fp16, warp tile 64x32 (r14, best).
// ---------------------------------------------------------------------------
template<typename TA, typename TC, int N>
__global__ __launch_bounds__(256, 2)
void h16_gemm(const TA* __restrict__ A, const uint32_t* __restrict__ Bw,
              const float* __restrict__ bias, TC* __restrict__ C)
{
    constexpr int K = 256, NT = 16, NBLK = N / 128;
    extern __shared__ uint32_t Asm[];

    const int tid  = threadIdx.x;
    const int lane = tid & 31;
    const int warp = tid >> 5;
    const int wm   = warp & 1;
    const int wn   = warp >> 1;
    const int bm   = blockIdx.x * 128;

    if constexpr (sizeof(TA) == 4) {
#pragma unroll
        for (int it = 0; it < 32; it++) {
            const int e = it * 256 + tid;
            const int row = e >> 6, c4 = e & 63;
            const int k = c4 * 4;
            const int kc = k >> 4;
            const int reg = ((row >> 3) & 1) + ((k >> 3) & 1) * 2;
            const int t0 = (k & 7) >> 1;
            const int mt = (row >> 4);
            const int g = row & 7;
            float4 v = *(const float4*)((const float*)A + (size_t)(bm + row) * K + k);
            uint2 w;
            w.x = pack_h2(v.x, v.y);
            w.y = pack_h2(v.z, v.w);
            *(uint2*)&Asm[((kc * 8 + mt) * 4 + reg) * 32 + g * 4 + t0] = w;
        }
    } else {
#pragma unroll
        for (int it = 0; it < 16; it++) {
            const int e = it * 256 + tid;
            const int row = e >> 5, c8 = e & 31;
            const int k = c8 * 8;
            const int kc = k >> 4;
            const int reg = ((row >> 3) & 1) + ((k >> 3) & 1) * 2;
            const int mt = (row >> 4);
            const int g = row & 7;
            uint4 v = *(const uint4*)((const __half*)A + (size_t)(bm + row) * K + k);
            *(uint4*)&Asm[((kc * 8 + mt) * 4 + reg) * 32 + g * 4] = v;
        }
    }
    __syncthreads();

    float acc[4][4][4];

    for (int nblk = 0; nblk < NBLK; nblk++) {
#pragma unroll
        for (int i = 0; i < 4; i++)
#pragma unroll
            for (int j = 0; j < 4; j++)
#pragma unroll
                for (int r = 0; r < 4; r++) acc[i][j][r] = 0.f;

        const uint32_t* bp = Bw + (size_t)nblk * 16384 + (wn * 8) * 32 + lane;

#pragma unroll
        for (int kc = 0; kc < NT; kc++) {
            uint32_t bf[8];
            const uint32_t* bk = bp + kc * 1024;
#pragma unroll
            for (int j = 0; j < 8; j++) bf[j] = __ldg(bk + j * 32);

            uint32_t af[4][4];
#pragma unroll
            for (int mt = 0; mt < 4; mt++) {
                const int base = ((kc * 8 + wm * 4 + mt) * 4) * 32 + lane;
#pragma unroll
                for (int r = 0; r < 4; r++) af[mt][r] = Asm[base + r * 32];
            }
#pragma unroll
            for (int mt = 0; mt < 4; mt++) {
#pragma unroll
                for (int nt = 0; nt < 4; nt++) {
                    asm volatile(
                        "mma.sync.aligned.m16n8k16.row.col.f32.f16.f16.f32 "
                        "{%0,%1,%2,%3}, {%4,%5,%6,%7}, {%8,%9}, {%0,%1,%2,%3};"
                        : "+f"(acc[mt][nt][0]), "+f"(acc[mt][nt][1]),
                          "+f"(acc[mt][nt][2]), "+f"(acc[mt][nt][3])
                        : "r"(af[mt][0]), "r"(af[mt][1]), "r"(af[mt][2]), "r"(af[mt][3]),
                          "r"(bf[nt * 2]), "r"(bf[nt * 2 + 1]));
                }
            }
        }

        const int g = lane >> 2, tig = lane & 3;
#pragma unroll
        for (int mt = 0; mt < 4; mt++) {
            const int r0 = bm + wm * 64 + mt * 16 + g;
#pragma unroll
            for (int nt = 0; nt < 4; nt++) {
                const int col = nblk * 128 + wn * 32 + nt * 8 + tig * 2;
                const float b0 = __ldg(bias + col);
                const float b1 = __ldg(bias + col + 1);
                __half* cp = (__half*)C;
                *(__half2*)(cp + (size_t)r0 * N + col) =
                    __floats2half2_rn(acc[mt][nt][0] + b0, acc[mt][nt][1] + b1);
                *(__half2*)(cp + (size_t)(r0 + 8) * N + col) =
                    __floats2half2_rn(acc[mt][nt][2] + b0, acc[mt][nt][3] + b1);
            }
        }
    }
}

// ---------------------------------------------------------------------------
// FUSED attention + projection. One block per window, 256 threads (8 warps).
// Phase 1: warp h does head h's attention (4 row-chunks); AV output written
//          straight into a phase-2 A-fragment smem image (layouts coincide).
// Phase 2: proj GEMM out[64x256] = Aimg @ Wp + bias, warp tile 32x64,
//          B from word-major g_wproj (L2-resident), fp32 output rows < 49.
// Smem word offsets: sq 0, sk 8448, svT 15840, sp 25056, Aimg 29664 (37856 w).
// ---------------------------------------------------------------------------
__global__ __launch_bounds__(256)
void attn_proj_fused(const __half* __restrict__ qkv,
                     const uint32_t* __restrict__ biasT,
                     const uint32_t* __restrict__ Wp,
                     const float* __restrict__ proj_b,
                     float* __restrict__ out)
{
    extern __shared__ uint32_t sm[];
    uint32_t* sq   = sm;                 // 64 rows x 132 words (256 halves + pad)
    uint32_t* sk   = sm + 8448;          // 56 rows x 132 words
    uint32_t* svT  = sm + 15840;         // 8 heads x 32 d-rows x 36 words
    uint32_t* sp   = sm + 25056;         // 8 warps x 16 rows x 36 words
    uint32_t* Aimg = sm + 29664;         // 16 kc x 4 mt x 4 reg x 32 lanes

    const int b    = blockIdx.x;
    const int tid  = threadIdx.x;
    const int lane = tid & 31;
    const int warp = tid >> 5;
    const int g = lane >> 2;
    const int t = lane & 3;

    const float scale = 0.17677669529663687f;
    const __half* base = qkv + (size_t)b * NTOK * 768;

    // ---- loads ---------------------------------------------------------------
    // q: 64 rows x 32 uint4 (full 256-half rows, clamped)
#pragma unroll
    for (int it = 0; it < 8; it++) {
        const int e = tid + it * 256;
        const int row = e >> 5, c = e & 31;
        const int sr = row < NTOK ? row : NTOK - 1;
        *(uint4*)&sq[row * 132 + c * 4] =
            *(const uint4*)(base + (size_t)sr * 768 + c * 8);
    }
    // k: 56 rows x 32 uint4
#pragma unroll
    for (int it = 0; it < 7; it++) {
        const int e = tid + it * 256;
        const int row = e >> 5, c = e & 31;
        const int sr = row < NTOK ? row : NTOK - 1;
        *(uint4*)&sk[row * 132 + c * 4] =
            *(const uint4*)(base + (size_t)sr * 768 + 256 + c * 8);
    }
    // V transpose per head: svT[h][d][tp] = half2(V[2tp][d], V[2tp+1][d])
#pragma unroll
    for (int it = 0; it < 4; it++) {
        const int e = tid + it * 256;
        if (e < 896) {
            const int h  = e / 112;
            const int r  = e - h * 112;
            const int tp = r >> 2, dg = r & 3;
            int t0 = 2 * tp, t1 = 2 * tp + 1;
            if (t0 > NTOK - 1) t0 = NTOK - 1;
            if (t1 > NTOK - 1) t1 = NTOK - 1;
            uint4 r0 = *(const uint4*)(base + (size_t)t0 * 768 + 512 + h * 32 + dg * 8);
            uint4 r1 = *(const uint4*)(base + (size_t)t1 * 768 + 512 + h * 32 + dg * 8);
            const __half* h0 = (const __half*)&r0;
            const __half* h1 = (const __half*)&r1;
#pragma unroll
            for (int i = 0; i < 8; i++) {
                __half2 w = __halves2half2(h0[i], h1[i]);
                svT[h * 1152 + (dg * 8 + i) * 36 + tp] = *(uint32_t*)&w;
            }
        }
    }
    // zero pads: svT tp 28..31 (8*32*4 = 1024 words), sp words 28..31 (8*16*4=512)
#pragma unroll
    for (int it = 0; it < 4; it++) {
        const int e = tid + it * 256;               // 0..1023
        svT[(e >> 2) * 36 + 28 + (e & 3)] = 0;
    }
    {
        const int e = tid;                           // 0..255 -> 2 words each
        sp[(e >> 1) * 36 + 28 + (e & 1) * 2]     = 0;
        sp[(e >> 1) * 36 + 28 + (e & 1) * 2 + 1] = 0;
    }
    __syncthreads();

    // ---- phase 1: warp = head; 4 row-chunks ----------------------------------
    const int h = warp;
    const int hw = h * 16;                           // head word offset in sq/sk rows
    uint32_t* spw = sp + warp * 576;                 // private P scratch (16 x 36)

#pragma unroll
    for (int c = 0; c < 4; c++) {
        const int mtb = c * 16;
        float sc[7][4];
#pragma unroll
        for (int nt = 0; nt < 7; nt++)
#pragma unroll
            for (int r = 0; r < 4; r++) sc[nt][r] = 0.f;

        // QK^T (fp16 mma, 2 ko)
#pragma unroll
        for (int ko = 0; ko < 2; ko++) {
            const uint32_t a0 = sq[(mtb + g) * 132 + hw + ko * 8 + t];
            const uint32_t a1 = sq[(mtb + g + 8) * 132 + hw + ko * 8 + t];
            const uint32_t a2 = sq[(mtb + g) * 132 + hw + ko * 8 + 4 + t];
            const uint32_t a3 = sq[(mtb + g + 8) * 132 + hw + ko * 8 + 4 + t];
#pragma unroll
            for (int nt = 0; nt < 7; nt++) {
                const uint32_t b0 = sk[(nt * 8 + g) * 132 + hw + ko * 8 + t];
                const uint32_t b1 = sk[(nt * 8 + g) * 132 + hw + ko * 8 + 4 + t];
                asm volatile(
                    "mma.sync.aligned.m16n8k16.row.col.f32.f16.f16.f32 "
                    "{%0,%1,%2,%3}, {%4,%5,%6,%7}, {%8,%9}, {%0,%1,%2,%3};"
                    : "+f"(sc[nt][0]), "+f"(sc[nt][1]), "+f"(sc[nt][2]), "+f"(sc[nt][3])
                    : "r"(a0), "r"(a1), "r"(a2), "r"(a3), "r"(b0), "r"(b1));
            }
        }

        // scale + bias + softmax
        const int i0 = mtb + g, i1 = i0 + 8;
        const uint4* bp0 = (const uint4*)biasT + (((h * 64 + i0) * 4 + t) * 2);
        const uint4* bp1 = (const uint4*)biasT + (((h * 64 + i1) * 4 + t) * 2);
        uint4 wa0 = __ldg(bp0), wb0 = __ldg(bp0 + 1);
        uint4 wa1 = __ldg(bp1), wb1 = __ldg(bp1 + 1);
        const uint32_t bw0[8] = {wa0.x, wa0.y, wa0.z, wa0.w, wb0.x, wb0.y, wb0.z, wb0.w};
        const uint32_t bw1[8] = {wa1.x, wa1.y, wa1.z, wa1.w, wb1.x, wb1.y, wb1.z, wb1.w};

        float m0 = -1e30f, m1 = -1e30f;
#pragma unroll
        for (int nt = 0; nt < 7; nt++) {
            const float2 f0 = __half22float2(*(const __half2*)&bw0[nt]);
            const float2 f1 = __half22float2(*(const __half2*)&bw1[nt]);
            sc[nt][0] = fmaf(sc[nt][0], scale, f0.x);
            sc[nt][1] = fmaf(sc[nt][1], scale, f0.y);
            sc[nt][2] = fmaf(sc[nt][2], scale, f1.x);
            sc[nt][3] = fmaf(sc[nt][3], scale, f1.y);
            m0 = fmaxf(m0, fmaxf(sc[nt][0], sc[nt][1]));
            m1 = fmaxf(m1, fmaxf(sc[nt][2], sc[nt][3]));
        }
        m0 = fmaxf(m0, __shfl_xor_sync(0xffffffffu, m0, 1));
        m0 = fmaxf(m0, __shfl_xor_sync(0xffffffffu, m0, 2));
        m1 = fmaxf(m1, __shfl_xor_sync(0xffffffffu, m1, 1));
        m1 = fmaxf(m1, __shfl_xor_sync(0xffffffffu, m1, 2));

        float s0 = 0.f, s1 = 0.f;
#pragma unroll
        for (int nt = 0; nt < 7; nt++) {
            float p0 = __expf(sc[nt][0] - m0);
            float p1 = __expf(sc[nt][1] - m0);
            float p2 = __expf(sc[nt][2] - m1);
            float p3 = __expf(sc[nt][3] - m1);
            sc[nt][0] = p0; sc[nt][1] = p1; sc[nt][2] = p2; sc[nt][3] = p3;
            s0 += p0 + p1;
            s1 += p2 + p3;
        }
        s0 += __shfl_xor_sync(0xffffffffu, s0, 1);
        s0 += __shfl_xor_sync(0xffffffffu, s0, 2);
        s1 += __shfl_xor_sync(0xffffffffu, s1, 1);
        s1 += __shfl_xor_sync(0xffffffffu, s1, 2);
        const float inv0 = 1.f / s0, inv1 = 1.f / s1;

        // P -> private smem (fp16 pairs along tokens)
#pragma unroll
        for (int nt = 0; nt < 7; nt++) {
            spw[g * 36 + nt * 4 + t]       = pack_h2(sc[nt][0], sc[nt][1]);
            spw[(g + 8) * 36 + nt * 4 + t] = pack_h2(sc[nt][2], sc[nt][3]);
        }
        __syncwarp();

        // AV (fp16 mma, 4 ko over padded K=64)
        float ov[4][4];
#pragma unroll
        for (int nt = 0; nt < 4; nt++)
#pragma unroll
            for (int r = 0; r < 4; r++) ov[nt][r] = 0.f;

#pragma unroll
        for (int ko = 0; ko < 4; ko++) {
            const uint32_t a0 = spw[g * 36 + ko * 8 + t];
            const uint32_t a1 = spw[(g + 8) * 36 + ko * 8 + t];
            const uint32_t a2 = spw[g * 36 + ko * 8 + 4 + t];
            const uint32_t a3 = spw[(g + 8) * 36 + ko * 8 + 4 + t];
#pragma unroll
            for (int nt = 0; nt < 4; nt++) {
                const uint32_t b0 = svT[h * 1152 + (nt * 8 + g) * 36 + ko * 8 + t];
                const uint32_t b1 = svT[h * 1152 + (nt * 8 + g) * 36 + ko * 8 + 4 + t];
                asm volatile(
                    "mma.sync.aligned.m16n8k16.row.col.f32.f16.f16.f32 "
                    "{%0,%1,%2,%3}, {%4,%5,%6,%7}, {%8,%9}, {%0,%1,%2,%3};"
                    : "+f"(ov[nt][0]), "+f"(ov[nt][1]), "+f"(ov[nt][2]), "+f"(ov[nt][3])
                    : "r"(a0), "r"(a1), "r"(a2), "r"(a3), "r"(b0), "r"(b1));
            }
        }
        __syncwarp();   // spw reuse safety across chunks

        // O -> phase-2 A-fragment image (normalized fp16)
        // k = h*32 + nt*8 + 2t  =>  kc = h*2 + (nt>>1), kh = nt&1
#pragma unroll
        for (int nt = 0; nt < 4; nt++) {
            const int kc = h * 2 + (nt >> 1);
            const int kh = nt & 1;
            const int addr0 = ((kc * 4 + c) * 4 + (0 + 2 * kh)) * 32 + g * 4 + t;
            const int addr1 = ((kc * 4 + c) * 4 + (1 + 2 * kh)) * 32 + g * 4 + t;
            Aimg[addr0] = pack_h2(ov[nt][0] * inv0, ov[nt][1] * inv0);
            Aimg[addr1] = pack_h2(ov[nt][2] * inv1, ov[nt][3] * inv1);
        }
    }
    __syncthreads();

    // ---- phase 2: proj GEMM out[64x256] = Aimg @ Wp + bias --------------------
    // warp: wm = w&1 (32-row half), wn = (w>>1)&1 (64-col half of nblk), nb = w>>2
    const int wm = warp & 1;
    const int wn = (warp >> 1) & 1;
    const int nb = warp >> 2;

    float acc[2][8][4];
#pragma unroll
    for (int i = 0; i < 2; i++)
#pragma unroll
        for (int j = 0; j < 8; j++)
#pragma unroll
            for (int r = 0; r < 4; r++) acc[i][j][r] = 0.f;

    const uint32_t* bp = Wp + (size_t)nb * 16384 + (wn * 16) * 32 + lane;

#pragma unroll
    for (int kc = 0; kc < 16; kc++) {
        uint32_t bf[16];
        const uint32_t* bk = bp + kc * 1024;
#pragma unroll
        for (int j = 0; j < 16; j++) bf[j] = __ldg(bk + j * 32);

        uint32_t af[2][4];
#pragma unroll
        for (int mt = 0; mt < 2; mt++) {
            const int bas = ((kc * 4 + wm * 2 + mt) * 4) * 32 + lane;
#pragma unroll
            for (int r = 0; r < 4; r++) af[mt][r] = Aimg[bas + r * 32];
        }
#pragma unroll
        for (int mt = 0; mt < 2; mt++) {
#pragma unroll
            for (int nt = 0; nt < 8; nt++) {
                const int j = (nt >> 2) * 8 + (nt & 3) * 2;
                asm volatile(
                    "mma.sync.aligned.m16n8k16.row.col.f32.f16.f16.f32 "
                    "{%0,%1,%2,%3}, {%4,%5,%6,%7}, {%8,%9}, {%0,%1,%2,%3};"
                    : "+f"(acc[mt][nt][0]), "+f"(acc[mt][nt][1]),
                      "+f"(acc[mt][nt][2]), "+f"(acc[mt][nt][3])
                    : "r"(af[mt][0]), "r"(af[mt][1]), "r"(af[mt][2]), "r"(af[mt][3]),
                      "r"(bf[j]), "r"(bf[j + 1]));
            }
        }
    }

    // epilogue: bias + fp32 store, rows < 49 only
    const int tig = lane & 3;
#pragma unroll
    for (int mt = 0; mt < 2; mt++) {
        const int r0 = wm * 32 + mt * 16 + g;
        const int r1 = r0 + 8;
#pragma unroll
        for (int nt = 0; nt < 8; nt++) {
            const int col = nb * 128 + (wn * 2 + (nt >> 2)) * 32 + (nt & 3) * 8 + tig * 2;
            const float b0 = __ldg(proj_b + col);
            const float b1 = __ldg(proj_b + col + 1);
            if (r0 < NTOK) {
                *(float2*)(out + ((size_t)b * NTOK + r0) * CDIM + col) =
                    make_float2(acc[mt][nt][0] + b0, acc[mt][nt][1] + b1);
            }
            if (r1 < NTOK) {
                *(float2*)(out + ((size_t)b * NTOK + r1) * CDIM + col) =
                    make_float2(acc[mt][nt][2] + b0, acc[mt][nt][3] + b1);
            }
        }
    }
}

// ---------------------------------------------------------------------------
// Launch
// ---------------------------------------------------------------------------
extern "C" void kernel_launch(void* const* d_in, const int* in_sizes, int n_in,
                              void* d_out, int out_size)
{
    const float* x      = (const float*)d_in[0];
    const float* qkv_w  = (const float*)d_in[1];
    const float* qkv_b  = (const float*)d_in[2];
    const float* rpb    = (const float*)d_in[3];
    const float* proj_w = (const float*)d_in[4];
    const float* proj_b = (const float*)d_in[5];
    float* out = (float*)d_out;

    __half* qkvh = nullptr;
    uint32_t* wqkv = nullptr;
    uint32_t* wproj = nullptr;
    uint32_t* biasT = nullptr;
    cudaGetSymbolAddress((void**)&qkvh, g_qkv);
    cudaGetSymbolAddress((void**)&wqkv, g_wqkv);
    cudaGetSymbolAddress((void**)&wproj, g_wproj);
    cudaGetSymbolAddress((void**)&biasT, g_bias);

    constexpr int SMEM_G = 16384 * 4;    // 64 KB (QKV GEMM A image)
    constexpr int SMEM_F = 37856 * 4;    // 151424 B (fused kernel)
    cudaFuncSetAttribute(h16_gemm<float, __half, 768>,
                         cudaFuncAttributeMaxDynamicSharedMemorySize, SMEM_G);
    cudaFuncSetAttribute(attn_proj_fused,
                         cudaFuncAttributeMaxDynamicSharedMemorySize, SMEM_F);

    // 0) one-time conversions (tiny)
    convert_w<<<384, 256>>>(qkv_w, wqkv, 768);
    convert_w<<<128, 256>>>(proj_w, wproj, 256);
    build_bias<<<64, 256>>>(rpb, biasT);

    // 1) QKV GEMM (barrier-free, 64x32 warp tile, fp16 out)
    h16_gemm<float, __half, 768><<<MROWS / 128, 256, SMEM_G>>>(x, wqkv, qkv_b, qkvh);

    // 2) FUSED attention + projection (writes fp32 output directly)
    attn_proj_fused<<<BWIN, 256, SMEM_F>>>(qkvh, biasT, wproj, proj_b, out);
}

// round 16
// speedup vs baseline: 1.0613x; 1.0613x over previous
#include <cuda_runtime.h>
#include <cuda_fp16.h>
#include <cstdint>

// Problem constants (fixed by setup_inputs)
#define BWIN   4096
#define NTOK   49
#define CDIM   256
#define NHEAD  8
#define MROWS  (BWIN * NTOK)   // 200704

// ---------------------------------------------------------------------------
// Scratch (device globals; no runtime allocation allowed)
// ---------------------------------------------------------------------------
__device__ __half   g_qkv[(size_t)MROWS * 768];
__device__ __half   g_att[(size_t)MROWS * CDIM];
__device__ uint32_t g_wqkv[6 * 16 * 32 * 32];        // word-major frag fp16 words
__device__ uint32_t g_wproj[2 * 16 * 32 * 32];
__device__ uint32_t g_bias[NHEAD * 64 * 32];         // [h][i][t][8] half2 words

__device__ __forceinline__ uint32_t pack_h2(float a, float b) {
    __half2 h = __floats2half2_rn(a, b);
    return *(uint32_t*)&h;
}

// ---------------------------------------------------------------------------
// Weight conversion: fp32 W[K,N] -> word-major fragment words (coalesced):
//   dst[((nblk*16 + kc)*32 + w)*32 + lane],  w = wq*8 + nt*2 + reg
//   lane = g*4 + t;  n = nblk*128 + wq*32 + nt*8 + g;  k = kc*16 + reg*8 + t*2
// ---------------------------------------------------------------------------
__global__ void convert_w(const float* __restrict__ w, uint32_t* __restrict__ dst, int N)
{
    const int idx  = blockIdx.x * 256 + threadIdx.x;
    const int lane = idx & 31;
    const int wrd  = (idx >> 5) & 31;
    const int kc   = (idx >> 10) & 15;
    const int nblk = idx >> 14;
    const int wq  = wrd >> 3;
    const int nt  = (wrd >> 1) & 3;
    const int reg = wrd & 1;
    const int g = lane >> 2, t = lane & 3;
    const int n = nblk * 128 + wq * 32 + nt * 8 + g;
    const int k = kc * 16 + reg * 8 + t * 2;
    dst[idx] = pack_h2(w[(size_t)k * N + n], w[(size_t)(k + 1) * N + n]);
}

// ---------------------------------------------------------------------------
// Bias+mask table: g_bias[((h*64+i)*4 + t)*8 + nt] = half2(B(i,j), B(i,j+1))
// ---------------------------------------------------------------------------
__global__ void build_bias(const float* __restrict__ rpb, uint32_t* __restrict__ dst)
{
    const int idx = blockIdx.x * 256 + threadIdx.x;
    const int nt = idx & 7;
    const int t  = (idx >> 3) & 3;
    const int i  = (idx >> 5) & 63;
    const int h  = idx >> 11;
    const int j0 = nt * 8 + 2 * t;
    float v[2];
#pragma unroll
    for (int e = 0; e < 2; e++) {
        const int j = j0 + e;
        if (i < NTOK && j < NTOK && nt < 7) {
            const int xi = i / 7, yi = i - xi * 7;
            const int xj = j / 7, yj = j - xj * 7;
            v[e] = rpb[((xi - xj + 6) * 13 + (yi - yj + 6)) * 8 + h];
        } else {
            v[e] = -10000.0f;
        }
    }
    dst[idx] = pack_h2(v[0], v[1]);
}

// ---------------------------------------------------------------------------
// QKV / proj GEMM: barrier-free A-resident fp16, warp tile 64x32 (r14, best).
// ---------------------------------------------------------------------------
template<typename TA, typename TC, int N>
__global__ __launch_bounds__(256, 2)
void h16_gemm(const TA* __restrict__ A, const uint32_t* __restrict__ Bw,
              const float* __restrict__ bias, TC* __restrict__ C)
{
    constexpr int K = 256, NT = 16, NBLK = N / 128;
    extern __shared__ uint32_t Asm[];

    const int tid  = threadIdx.x;
    const int lane = tid & 31;
    const int warp = tid >> 5;
    const int wm   = warp & 1;
    const int wn   = warp >> 1;
    const int bm   = blockIdx.x * 128;

    if constexpr (sizeof(TA) == 4) {
#pragma unroll
        for (int it = 0; it < 32; it++) {
            const int e = it * 256 + tid;
            const int row = e >> 6, c4 = e & 63;
            const int k = c4 * 4;
            const int kc = k >> 4;
            const int reg = ((row >> 3) & 1) + ((k >> 3) & 1) * 2;
            const int t0 = (k & 7) >> 1;
            const int mt = (row >> 4);
            const int g = row & 7;
            float4 v = *(const float4*)((const float*)A + (size_t)(bm + row) * K + k);
            uint2 w;
            w.x = pack_h2(v.x, v.y);
            w.y = pack_h2(v.z, v.w);
            *(uint2*)&Asm[((kc * 8 + mt) * 4 + reg) * 32 + g * 4 + t0] = w;
        }
    } else {
#pragma unroll
        for (int it = 0; it < 16; it++) {
            const int e = it * 256 + tid;
            const int row = e >> 5, c8 = e & 31;
            const int k = c8 * 8;
            const int kc = k >> 4;
            const int reg = ((row >> 3) & 1) + ((k >> 3) & 1) * 2;
            const int mt = (row >> 4);
            const int g = row & 7;
            uint4 v = *(const uint4*)((const __half*)A + (size_t)(bm + row) * K + k);
            *(uint4*)&Asm[((kc * 8 + mt) * 4 + reg) * 32 + g * 4] = v;
        }
    }
    __syncthreads();

    float acc[4][4][4];

    for (int nblk = 0; nblk < NBLK; nblk++) {
#pragma unroll
        for (int i = 0; i < 4; i++)
#pragma unroll
            for (int j = 0; j < 4; j++)
#pragma unroll
                for (int r = 0; r < 4; r++) acc[i][j][r] = 0.f;

        const uint32_t* bp = Bw + (size_t)nblk * 16384 + (wn * 8) * 32 + lane;

#pragma unroll
        for (int kc = 0; kc < NT; kc++) {
            uint32_t bf[8];
            const uint32_t* bk = bp + kc * 1024;
#pragma unroll
            for (int j = 0; j < 8; j++) bf[j] = __ldg(bk + j * 32);

            uint32_t af[4][4];
#pragma unroll
            for (int mt = 0; mt < 4; mt++) {
                const int base = ((kc * 8 + wm * 4 + mt) * 4) * 32 + lane;
#pragma unroll
                for (int r = 0; r < 4; r++) af[mt][r] = Asm[base + r * 32];
            }
#pragma unroll
            for (int mt = 0; mt < 4; mt++) {
#pragma unroll
                for (int nt = 0; nt < 4; nt++) {
                    asm volatile(
                        "mma.sync.aligned.m16n8k16.row.col.f32.f16.f16.f32 "
                        "{%0,%1,%2,%3}, {%4,%5,%6,%7}, {%8,%9}, {%0,%1,%2,%3};"
                        : "+f"(acc[mt][nt][0]), "+f"(acc[mt][nt][1]),
                          "+f"(acc[mt][nt][2]), "+f"(acc[mt][nt][3])
                        : "r"(af[mt][0]), "r"(af[mt][1]), "r"(af[mt][2]), "r"(af[mt][3]),
                          "r"(bf[nt * 2]), "r"(bf[nt * 2 + 1]));
                }
            }
        }

        const int g = lane >> 2, tig = lane & 3;
#pragma unroll
        for (int mt = 0; mt < 4; mt++) {
            const int r0 = bm + wm * 64 + mt * 16 + g;
#pragma unroll
            for (int nt = 0; nt < 4; nt++) {
                const int col = nblk * 128 + wn * 32 + nt * 8 + tig * 2;
                const float b0 = __ldg(bias + col);
                const float b1 = __ldg(bias + col + 1);
                if constexpr (sizeof(TC) == 2) {
                    __half* cp = (__half*)C;
                    *(__half2*)(cp + (size_t)r0 * N + col) =
                        __floats2half2_rn(acc[mt][nt][0] + b0, acc[mt][nt][1] + b1);
                    *(__half2*)(cp + (size_t)(r0 + 8) * N + col) =
                        __floats2half2_rn(acc[mt][nt][2] + b0, acc[mt][nt][3] + b1);
                } else {
                    float* cp = (float*)C;
                    *(float2*)(cp + (size_t)r0 * N + col) =
                        make_float2(acc[mt][nt][0] + b0, acc[mt][nt][1] + b1);
                    *(float2*)(cp + (size_t)(r0 + 8) * N + col) =
                        make_float2(acc[mt][nt][2] + b0, acc[mt][nt][3] + b1);
                }
            }
        }
    }
}

// ---------------------------------------------------------------------------
// fp16 tensor-core windowed attention, REGISTER-DIRECT P:
// the QK accumulator layout IS the AV A-fragment layout (same lane holds the
// same (row, col-pair) elements), so exp(S) never touches smem — AV A-frags
// are pure register repacks. sp smem, its zero-fill, 14 STS + 16 LDS and the
// intra-chunk syncwarps are all gone vs r14.
// ---------------------------------------------------------------------------
__global__ __launch_bounds__(128)
void window_attn_h16(const __half* __restrict__ qkv,
                     const uint32_t* __restrict__ biasT,
                     __half* __restrict__ out)
{
    __shared__ uint32_t sq [64 * 36];
    __shared__ uint32_t sk [56 * 36];
    __shared__ uint32_t svT[32 * 36];

    const int b = blockIdx.x;
    const int h = blockIdx.y;
    const int tid  = threadIdx.x;
    const int lane = tid & 31;
    const int warp = tid >> 5;
    const int g = lane >> 2;
    const int t = lane & 3;

    const float scale = 0.17677669529663687f;
    const __half* base = qkv + (size_t)b * NTOK * 768 + h * 32;

#pragma unroll
    for (int it = 0; it < 2; it++) {
        const int e = tid + it * 128;
        const int row = e >> 2, c = e & 3;
        const int sr = row < NTOK ? row : NTOK - 1;
        *(uint4*)&sq[row * 36 + c * 4] =
            *(const uint4*)(base + (size_t)sr * 768 + c * 8);
    }
#pragma unroll
    for (int it = 0; it < 2; it++) {
        const int e = tid + it * 128;
        if (e < 224) {
            const int row = e >> 2, c = e & 3;
            const int sr = row < NTOK ? row : NTOK - 1;
            *(uint4*)&sk[row * 36 + c * 4] =
                *(const uint4*)(base + (size_t)sr * 768 + 256 + c * 8);
        }
    }
    if (tid < 112) {
        const int tp = tid >> 2, dg = tid & 3;
        int t0 = 2 * tp, t1 = 2 * tp + 1;
        if (t0 > NTOK - 1) t0 = NTOK - 1;
        if (t1 > NTOK - 1) t1 = NTOK - 1;
        uint4 r0 = *(const uint4*)(base + (size_t)t0 * 768 + 512 + dg * 8);
        uint4 r1 = *(const uint4*)(base + (size_t)t1 * 768 + 512 + dg * 8);
        const __half* h0 = (const __half*)&r0;
        const __half* h1 = (const __half*)&r1;
#pragma unroll
        for (int i = 0; i < 8; i++) {
            __half2 w = __halves2half2(h0[i], h1[i]);
            svT[(dg * 8 + i) * 36 + tp] = *(uint32_t*)&w;
        }
    }
    // zero V padding (token pairs 28..31)
    svT[(tid >> 2) * 36 + 28 + (tid & 3)] = 0;
    __syncthreads();

    // ---- QK^T: warp computes S[16 x 56] (fp16 mma, 2 ko) ----------------------
    const int mtb = warp * 16;
    float sc[8][4];                       // nt = 7 stays zero (K padding for AV)
#pragma unroll
    for (int nt = 0; nt < 8; nt++)
#pragma unroll
        for (int r = 0; r < 4; r++) sc[nt][r] = 0.f;

#pragma unroll
    for (int ko = 0; ko < 2; ko++) {
        const uint32_t a0 = sq[(mtb + g) * 36 + ko * 8 + t];
        const uint32_t a1 = sq[(mtb + g + 8) * 36 + ko * 8 + t];
        const uint32_t a2 = sq[(mtb + g) * 36 + ko * 8 + 4 + t];
        const uint32_t a3 = sq[(mtb + g + 8) * 36 + ko * 8 + 4 + t];
#pragma unroll
        for (int nt = 0; nt < 7; nt++) {
            const uint32_t b0 = sk[(nt * 8 + g) * 36 + ko * 8 + t];
            const uint32_t b1 = sk[(nt * 8 + g) * 36 + ko * 8 + 4 + t];
            asm volatile(
                "mma.sync.aligned.m16n8k16.row.col.f32.f16.f16.f32 "
                "{%0,%1,%2,%3}, {%4,%5,%6,%7}, {%8,%9}, {%0,%1,%2,%3};"
                : "+f"(sc[nt][0]), "+f"(sc[nt][1]), "+f"(sc[nt][2]), "+f"(sc[nt][3])
                : "r"(a0), "r"(a1), "r"(a2), "r"(a3), "r"(b0), "r"(b1));
        }
    }

    // ---- scale + bias + softmax (in registers) --------------------------------
    const int i0 = mtb + g, i1 = i0 + 8;
    const uint4* bp0 = (const uint4*)biasT + (((h * 64 + i0) * 4 + t) * 2);
    const uint4* bp1 = (const uint4*)biasT + (((h * 64 + i1) * 4 + t) * 2);
    uint4 wa0 = __ldg(bp0), wb0 = __ldg(bp0 + 1);
    uint4 wa1 = __ldg(bp1), wb1 = __ldg(bp1 + 1);
    const uint32_t bw0[8] = {wa0.x, wa0.y, wa0.z, wa0.w, wb0.x, wb0.y, wb0.z, wb0.w};
    const uint32_t bw1[8] = {wa1.x, wa1.y, wa1.z, wa1.w, wb1.x, wb1.y, wb1.z, wb1.w};

    float m0 = -1e30f, m1 = -1e30f;
#pragma unroll
    for (int nt = 0; nt < 7; nt++) {
        const float2 f0 = __half22float2(*(const __half2*)&bw0[nt]);
        const float2 f1 = __half22float2(*(const __half2*)&bw1[nt]);
        sc[nt][0] = fmaf(sc[nt][0], scale, f0.x);
        sc[nt][1] = fmaf(sc[nt][1], scale, f0.y);
        sc[nt][2] = fmaf(sc[nt][2], scale, f1.x);
        sc[nt][3] = fmaf(sc[nt][3], scale, f1.y);
        m0 = fmaxf(m0, fmaxf(sc[nt][0], sc[nt][1]));
        m1 = fmaxf(m1, fmaxf(sc[nt][2], sc[nt][3]));
    }
    m0 = fmaxf(m0, __shfl_xor_sync(0xffffffffu, m0, 1));
    m0 = fmaxf(m0, __shfl_xor_sync(0xffffffffu, m0, 2));
    m1 = fmaxf(m1, __shfl_xor_sync(0xffffffffu, m1, 1));
    m1 = fmaxf(m1, __shfl_xor_sync(0xffffffffu, m1, 2));

    float s0 = 0.f, s1 = 0.f;
#pragma unroll
    for (int nt = 0; nt < 7; nt++) {
        float p0 = __expf(sc[nt][0] - m0);
        float p1 = __expf(sc[nt][1] - m0);
        float p2 = __expf(sc[nt][2] - m1);
        float p3 = __expf(sc[nt][3] - m1);
        sc[nt][0] = p0; sc[nt][1] = p1; sc[nt][2] = p2; sc[nt][3] = p3;
        s0 += p0 + p1;
        s1 += p2 + p3;
    }
    s0 += __shfl_xor_sync(0xffffffffu, s0, 1);
    s0 += __shfl_xor_sync(0xffffffffu, s0, 2);
    s1 += __shfl_xor_sync(0xffffffffu, s1, 1);
    s1 += __shfl_xor_sync(0xffffffffu, s1, 2);
    const float inv0 = 1.f / s0, inv1 = 1.f / s1;

    // ---- AV: A-fragments ARE the (packed) accumulators -------------------------
    float ov[4][4];
#pragma unroll
    for (int nt = 0; nt < 4; nt++)
#pragma unroll
        for (int r = 0; r < 4; r++) ov[nt][r] = 0.f;

#pragma unroll
    for (int ko = 0; ko < 4; ko++) {
        const uint32_t a0 = pack_h2(sc[2 * ko][0],     sc[2 * ko][1]);
        const uint32_t a1 = pack_h2(sc[2 * ko][2],     sc[2 * ko][3]);
        const uint32_t a2 = pack_h2(sc[2 * ko + 1][0], sc[2 * ko + 1][1]);
        const uint32_t a3 = pack_h2(sc[2 * ko + 1][2], sc[2 * ko + 1][3]);
#pragma unroll
        for (int nt = 0; nt < 4; nt++) {
            const uint32_t b0 = svT[(nt * 8 + g) * 36 + ko * 8 + t];
            const uint32_t b1 = svT[(nt * 8 + g) * 36 + ko * 8 + 4 + t];
            asm volatile(
                "mma.sync.aligned.m16n8k16.row.col.f32.f16.f16.f32 "
                "{%0,%1,%2,%3}, {%4,%5,%6,%7}, {%8,%9}, {%0,%1,%2,%3};"
                : "+f"(ov[nt][0]), "+f"(ov[nt][1]), "+f"(ov[nt][2]), "+f"(ov[nt][3])
                : "r"(a0), "r"(a1), "r"(a2), "r"(a3), "r"(b0), "r"(b1));
        }
    }

    // ---- output (fp16, normalized) ----------------------------------------------
    const bool v0 = i0 < NTOK, v1 = i1 < NTOK;
#pragma unroll
    for (int nt = 0; nt < 4; nt++) {
        const int col = h * 32 + nt * 8 + 2 * t;
        if (v0) {
            *(__half2*)(out + ((size_t)b * NTOK + i0) * CDIM + col) =
                __floats2half2_rn(ov[nt][0] * inv0, ov[nt][1] * inv0);
        }
        if (v1) {
            *(__half2*)(out + ((size_t)b * NTOK + i1) * CDIM + col) =
                __floats2half2_rn(ov[nt][2] * inv1, ov[nt][3] * inv1);
        }
    }
}

// ---------------------------------------------------------------------------
// Launch
// ---------------------------------------------------------------------------
extern "C" void kernel_launch(void* const* d_in, const int* in_sizes, int n_in,
                              void* d_out, int out_size)
{
    const float* x      = (const float*)d_in[0];
    const float* qkv_w  = (const float*)d_in[1];
    const float* qkv_b  = (const float*)d_in[2];
    const float* rpb    = (const float*)d_in[3];
    const float* proj_w = (const float*)d_in[4];
    const float* proj_b = (const float*)d_in[5];
    float* out = (float*)d_out;

    __half* qkvh = nullptr;
    __half* atth = nullptr;
    uint32_t* wqkv = nullptr;
    uint32_t* wproj = nullptr;
    uint32_t* biasT = nullptr;
    cudaGetSymbolAddress((void**)&qkvh, g_qkv);
    cudaGetSymbolAddress((void**)&atth, g_att);
    cudaGetSymbolAddress((void**)&wqkv, g_wqkv);
    cudaGetSymbolAddress((void**)&wproj, g_wproj);
    cudaGetSymbolAddress((void**)&biasT, g_bias);

    constexpr int SMEM = 16384 * 4;   // 64 KB (A fragment image)
    cudaFuncSetAttribute(h16_gemm<float, __half, 768>,
                         cudaFuncAttributeMaxDynamicSharedMemorySize, SMEM);
    cudaFuncSetAttribute(h16_gemm<__half, float, 256>,
                         cudaFuncAttributeMaxDynamicSharedMemorySize, SMEM);

    // 0) one-time conversions (tiny)
    convert_w<<<384, 256>>>(qkv_w, wqkv, 768);
    convert_w<<<128, 256>>>(proj_w, wproj, 256);
    build_bias<<<64, 256>>>(rpb, biasT);

    // 1) QKV GEMM (barrier-free, 64x32 warp tile, fp16 out)
    h16_gemm<float, __half, 768><<<MROWS / 128, 256, SMEM>>>(x, wqkv, qkv_b, qkvh);

    // 2) Windowed attention (register-direct P)
    {
        dim3 grid(BWIN, NHEAD);
        window_attn_h16<<<grid, 128>>>(qkvh, biasT, atth);
    }

    // 3) Projection GEMM (barrier-free, 64x32 warp tile, fp32 out)
    h16_gemm<__half, float, 256><<<MROWS / 128, 256, SMEM>>>(atth, wproj, proj_b, out);
}

// round 17
// speedup vs baseline: 1.0617x; 1.0004x over previous
#include <cuda_runtime.h>
#include <cuda_fp16.h>
#include <cstdint>

// Problem constants (fixed by setup_inputs)
#define BWIN   4096
#define NTOK   49
#define CDIM   256
#define NHEAD  8
#define MROWS  (BWIN * NTOK)   // 200704

#define NCHUNK 4
#define WCH    (BWIN / NCHUNK)          // 1024 windows per chunk
#define RCH    (WCH * NTOK)             // 50176 rows per chunk (392 * 128)

// ---------------------------------------------------------------------------
// Scratch (device globals; no runtime allocation allowed)
// ---------------------------------------------------------------------------
__device__ __half   g_qkv[(size_t)MROWS * 768];
__device__ __half   g_att[(size_t)MROWS * CDIM];
__device__ uint32_t g_wqkv[6 * 16 * 32 * 32];        // word-major frag fp16 words
__device__ uint32_t g_wproj[2 * 16 * 32 * 32];
__device__ uint32_t g_bias[NHEAD * 64 * 32];         // [h][i][t][8] half2 words

__device__ __forceinline__ uint32_t pack_h2(float a, float b) {
    __half2 h = __floats2half2_rn(a, b);
    return *(uint32_t*)&h;
}

// ---------------------------------------------------------------------------
// Weight conversion: fp32 W[K,N] -> word-major fragment words (coalesced)
// ---------------------------------------------------------------------------
__global__ void convert_w(const float* __restrict__ w, uint32_t* __restrict__ dst, int N)
{
    const int idx  = blockIdx.x * 256 + threadIdx.x;
    const int lane = idx & 31;
    const int wrd  = (idx >> 5) & 31;
    const int kc   = (idx >> 10) & 15;
    const int nblk = idx >> 14;
    const int wq  = wrd >> 3;
    const int nt  = (wrd >> 1) & 3;
    const int reg = wrd & 1;
    const int g = lane >> 2, t = lane & 3;
    const int n = nblk * 128 + wq * 32 + nt * 8 + g;
    const int k = kc * 16 + reg * 8 + t * 2;
    dst[idx] = pack_h2(w[(size_t)k * N + n], w[(size_t)(k + 1) * N + n]);
}

// ---------------------------------------------------------------------------
// Bias+mask table: g_bias[((h*64+i)*4 + t)*8 + nt] = half2(B(i,j), B(i,j+1))
// ---------------------------------------------------------------------------
__global__ void build_bias(const float* __restrict__ rpb, uint32_t* __restrict__ dst)
{
    const int idx = blockIdx.x * 256 + threadIdx.x;
    const int nt = idx & 7;
    const int t  = (idx >> 3) & 3;
    const int i  = (idx >> 5) & 63;
    const int h  = idx >> 11;
    const int j0 = nt * 8 + 2 * t;
    float v[2];
#pragma unroll
    for (int e = 0; e < 2; e++) {
        const int j = j0 + e;
        if (i < NTOK && j < NTOK && nt < 7) {
            const int xi = i / 7, yi = i - xi * 7;
            const int xj = j / 7, yj = j - xj * 7;
            v[e] = rpb[((xi - xj + 6) * 13 + (yi - yj + 6)) * 8 + h];
        } else {
            v[e] = -10000.0f;
        }
    }
    dst[idx] = pack_h2(v[0], v[1]);
}

// ---------------------------------------------------------------------------
// QKV / proj GEMM: barrier-free A-resident fp16, warp tile 64x32 (r14/r16).
// ---------------------------------------------------------------------------
template<typename TA, typename TC, int N>
__global__ __launch_bounds__(256, 2)
void h16_gemm(const TA* __restrict__ A, const uint32_t* __restrict__ Bw,
              const float* __restrict__ bias, TC* __restrict__ C)
{
    constexpr int K = 256, NT = 16, NBLK = N / 128;
    extern __shared__ uint32_t Asm[];

    const int tid  = threadIdx.x;
    const int lane = tid & 31;
    const int warp = tid >> 5;
    const int wm   = warp & 1;
    const int wn   = warp >> 1;
    const int bm   = blockIdx.x * 128;

    if constexpr (sizeof(TA) == 4) {
#pragma unroll
        for (int it = 0; it < 32; it++) {
            const int e = it * 256 + tid;
            const int row = e >> 6, c4 = e & 63;
            const int k = c4 * 4;
            const int kc = k >> 4;
            const int reg = ((row >> 3) & 1) + ((k >> 3) & 1) * 2;
            const int t0 = (k & 7) >> 1;
            const int mt = (row >> 4);
            const int g = row & 7;
            float4 v = *(const float4*)((const float*)A + (size_t)(bm + row) * K + k);
            uint2 w;
            w.x = pack_h2(v.x, v.y);
            w.y = pack_h2(v.z, v.w);
            *(uint2*)&Asm[((kc * 8 + mt) * 4 + reg) * 32 + g * 4 + t0] = w;
        }
    } else {
#pragma unroll
        for (int it = 0; it < 16; it++) {
            const int e = it * 256 + tid;
            const int row = e >> 5, c8 = e & 31;
            const int k = c8 * 8;
            const int kc = k >> 4;
            const int reg = ((row >> 3) & 1) + ((k >> 3) & 1) * 2;
            const int mt = (row >> 4);
            const int g = row & 7;
            uint4 v = *(const uint4*)((const __half*)A + (size_t)(bm + row) * K + k);
            *(uint4*)&Asm[((kc * 8 + mt) * 4 + reg) * 32 + g * 4] = v;
        }
    }
    __syncthreads();

    float acc[4][4][4];

    for (int nblk = 0; nblk < NBLK; nblk++) {
#pragma unroll
        for (int i = 0; i < 4; i++)
#pragma unroll
            for (int j = 0; j < 4; j++)
#pragma unroll
                for (int r = 0; r < 4; r++) acc[i][j][r] = 0.f;

        const uint32_t* bp = Bw + (size_t)nblk * 16384 + (wn * 8) * 32 + lane;

#pragma unroll
        for (int kc = 0; kc < NT; kc++) {
            uint32_t bf[8];
            const uint32_t* bk = bp + kc * 1024;
#pragma unroll
            for (int j = 0; j < 8; j++) bf[j] = __ldg(bk + j * 32);

            uint32_t af[4][4];
#pragma unroll
            for (int mt = 0; mt < 4; mt++) {
                const int base = ((kc * 8 + wm * 4 + mt) * 4) * 32 + lane;
#pragma unroll
                for (int r = 0; r < 4; r++) af[mt][r] = Asm[base + r * 32];
            }
#pragma unroll
            for (int mt = 0; mt < 4; mt++) {
#pragma unroll
                for (int nt = 0; nt < 4; nt++) {
                    asm volatile(
                        "mma.sync.aligned.m16n8k16.row.col.f32.f16.f16.f32 "
                        "{%0,%1,%2,%3}, {%4,%5,%6,%7}, {%8,%9}, {%0,%1,%2,%3};"
                        : "+f"(acc[mt][nt][0]), "+f"(acc[mt][nt][1]),
                          "+f"(acc[mt][nt][2]), "+f"(acc[mt][nt][3])
                        : "r"(af[mt][0]), "r"(af[mt][1]), "r"(af[mt][2]), "r"(af[mt][3]),
                          "r"(bf[nt * 2]), "r"(bf[nt * 2 + 1]));
                }
            }
        }

        const int g = lane >> 2, tig = lane & 3;
#pragma unroll
        for (int mt = 0; mt < 4; mt++) {
            const int r0 = bm + wm * 64 + mt * 16 + g;
#pragma unroll
            for (int nt = 0; nt < 4; nt++) {
                const int col = nblk * 128 + wn * 32 + nt * 8 + tig * 2;
                const float b0 = __ldg(bias + col);
                const float b1 = __ldg(bias + col + 1);
                if constexpr (sizeof(TC) == 2) {
                    __half* cp = (__half*)C;
                    *(__half2*)(cp + (size_t)r0 * N + col) =
                        __floats2half2_rn(acc[mt][nt][0] + b0, acc[mt][nt][1] + b1);
                    *(__half2*)(cp + (size_t)(r0 + 8) * N + col) =
                        __floats2half2_rn(acc[mt][nt][2] + b0, acc[mt][nt][3] + b1);
                } else {
                    float* cp = (float*)C;
                    *(float2*)(cp + (size_t)r0 * N + col) =
                        make_float2(acc[mt][nt][0] + b0, acc[mt][nt][1] + b1);
                    *(float2*)(cp + (size_t)(r0 + 8) * N + col) =
                        make_float2(acc[mt][nt][2] + b0, acc[mt][nt][3] + b1);
                }
            }
        }
    }
}

// ---------------------------------------------------------------------------
// fp16 tensor-core windowed attention, register-direct P (r16).
// ---------------------------------------------------------------------------
__global__ __launch_bounds__(128)
void window_attn_h16(const __half* __restrict__ qkv,
                     const uint32_t* __restrict__ biasT,
                     __half* __restrict__ out)
{
    __shared__ uint32_t sq [64 * 36];
    __shared__ uint32_t sk [56 * 36];
    __shared__ uint32_t svT[32 * 36];

    const int b = blockIdx.x;
    const int h = blockIdx.y;
    const int tid  = threadIdx.x;
    const int lane = tid & 31;
    const int warp = tid >> 5;
    const int g = lane >> 2;
    const int t = lane & 3;

    const float scale = 0.17677669529663687f;
    const __half* base = qkv + (size_t)b * NTOK * 768 + h * 32;

#pragma unroll
    for (int it = 0; it < 2; it++) {
        const int e = tid + it * 128;
        const int row = e >> 2, c = e & 3;
        const int sr = row < NTOK ? row : NTOK - 1;
        *(uint4*)&sq[row * 36 + c * 4] =
            *(const uint4*)(base + (size_t)sr * 768 + c * 8);
    }
#pragma unroll
    for (int it = 0; it < 2; it++) {
        const int e = tid + it * 128;
        if (e < 224) {
            const int row = e >> 2, c = e & 3;
            const int sr = row < NTOK ? row : NTOK - 1;
            *(uint4*)&sk[row * 36 + c * 4] =
                *(const uint4*)(base + (size_t)sr * 768 + 256 + c * 8);
        }
    }
    if (tid < 112) {
        const int tp = tid >> 2, dg = tid & 3;
        int t0 = 2 * tp, t1 = 2 * tp + 1;
        if (t0 > NTOK - 1) t0 = NTOK - 1;
        if (t1 > NTOK - 1) t1 = NTOK - 1;
        uint4 r0 = *(const uint4*)(base + (size_t)t0 * 768 + 512 + dg * 8);
        uint4 r1 = *(const uint4*)(base + (size_t)t1 * 768 + 512 + dg * 8);
        const __half* h0 = (const __half*)&r0;
        const __half* h1 = (const __half*)&r1;
#pragma unroll
        for (int i = 0; i < 8; i++) {
            __half2 w = __halves2half2(h0[i], h1[i]);
            svT[(dg * 8 + i) * 36 + tp] = *(uint32_t*)&w;
        }
    }
    svT[(tid >> 2) * 36 + 28 + (tid & 3)] = 0;
    __syncthreads();

    const int mtb = warp * 16;
    float sc[8][4];
#pragma unroll
    for (int nt = 0; nt < 8; nt++)
#pragma unroll
        for (int r = 0; r < 4; r++) sc[nt][r] = 0.f;

#pragma unroll
    for (int ko = 0; ko < 2; ko++) {
        const uint32_t a0 = sq[(mtb + g) * 36 + ko * 8 + t];
        const uint32_t a1 = sq[(mtb + g + 8) * 36 + ko * 8 + t];
        const uint32_t a2 = sq[(mtb + g) * 36 + ko * 8 + 4 + t];
        const uint32_t a3 = sq[(mtb + g + 8) * 36 + ko * 8 + 4 + t];
#pragma unroll
        for (int nt = 0; nt < 7; nt++) {
            const uint32_t b0 = sk[(nt * 8 + g) * 36 + ko * 8 + t];
            const uint32_t b1 = sk[(nt * 8 + g) * 36 + ko * 8 + 4 + t];
            asm volatile(
                "mma.sync.aligned.m16n8k16.row.col.f32.f16.f16.f32 "
                "{%0,%1,%2,%3}, {%4,%5,%6,%7}, {%8,%9}, {%0,%1,%2,%3};"
                : "+f"(sc[nt][0]), "+f"(sc[nt][1]), "+f"(sc[nt][2]), "+f"(sc[nt][3])
                : "r"(a0), "r"(a1), "r"(a2), "r"(a3), "r"(b0), "r"(b1));
        }
    }

    const int i0 = mtb + g, i1 = i0 + 8;
    const uint4* bp0 = (const uint4*)biasT + (((h * 64 + i0) * 4 + t) * 2);
    const uint4* bp1 = (const uint4*)biasT + (((h * 64 + i1) * 4 + t) * 2);
    uint4 wa0 = __ldg(bp0), wb0 = __ldg(bp0 + 1);
    uint4 wa1 = __ldg(bp1), wb1 = __ldg(bp1 + 1);
    const uint32_t bw0[8] = {wa0.x, wa0.y, wa0.z, wa0.w, wb0.x, wb0.y, wb0.z, wb0.w};
    const uint32_t bw1[8] = {wa1.x, wa1.y, wa1.z, wa1.w, wb1.x, wb1.y, wb1.z, wb1.w};

    float m0 = -1e30f, m1 = -1e30f;
#pragma unroll
    for (int nt = 0; nt < 7; nt++) {
        const float2 f0 = __half22float2(*(const __half2*)&bw0[nt]);
        const float2 f1 = __half22float2(*(const __half2*)&bw1[nt]);
        sc[nt][0] = fmaf(sc[nt][0], scale, f0.x);
        sc[nt][1] = fmaf(sc[nt][1], scale, f0.y);
        sc[nt][2] = fmaf(sc[nt][2], scale, f1.x);
        sc[nt][3] = fmaf(sc[nt][3], scale, f1.y);
        m0 = fmaxf(m0, fmaxf(sc[nt][0], sc[nt][1]));
        m1 = fmaxf(m1, fmaxf(sc[nt][2], sc[nt][3]));
    }
    m0 = fmaxf(m0, __shfl_xor_sync(0xffffffffu, m0, 1));
    m0 = fmaxf(m0, __shfl_xor_sync(0xffffffffu, m0, 2));
    m1 = fmaxf(m1, __shfl_xor_sync(0xffffffffu, m1, 1));
    m1 = fmaxf(m1, __shfl_xor_sync(0xffffffffu, m1, 2));

    float s0 = 0.f, s1 = 0.f;
#pragma unroll
    for (int nt = 0; nt < 7; nt++) {
        float p0 = __expf(sc[nt][0] - m0);
        float p1 = __expf(sc[nt][1] - m0);
        float p2 = __expf(sc[nt][2] - m1);
        float p3 = __expf(sc[nt][3] - m1);
        sc[nt][0] = p0; sc[nt][1] = p1; sc[nt][2] = p2; sc[nt][3] = p3;
        s0 += p0 + p1;
        s1 += p2 + p3;
    }
    s0 += __shfl_xor_sync(0xffffffffu, s0, 1);
    s0 += __shfl_xor_sync(0xffffffffu, s0, 2);
    s1 += __shfl_xor_sync(0xffffffffu, s1, 1);
    s1 += __shfl_xor_sync(0xffffffffu, s1, 2);
    const float inv0 = 1.f / s0, inv1 = 1.f / s1;

    float ov[4][4];
#pragma unroll
    for (int nt = 0; nt < 4; nt++)
#pragma unroll
        for (int r = 0; r < 4; r++) ov[nt][r] = 0.f;

#pragma unroll
    for (int ko = 0; ko < 4; ko++) {
        const uint32_t a0 = pack_h2(sc[2 * ko][0],     sc[2 * ko][1]);
        const uint32_t a1 = pack_h2(sc[2 * ko][2],     sc[2 * ko][3]);
        const uint32_t a2 = pack_h2(sc[2 * ko + 1][0], sc[2 * ko + 1][1]);
        const uint32_t a3 = pack_h2(sc[2 * ko + 1][2], sc[2 * ko + 1][3]);
#pragma unroll
        for (int nt = 0; nt < 4; nt++) {
            const uint32_t b0 = svT[(nt * 8 + g) * 36 + ko * 8 + t];
            const uint32_t b1 = svT[(nt * 8 + g) * 36 + ko * 8 + 4 + t];
            asm volatile(
                "mma.sync.aligned.m16n8k16.row.col.f32.f16.f16.f32 "
                "{%0,%1,%2,%3}, {%4,%5,%6,%7}, {%8,%9}, {%0,%1,%2,%3};"
                : "+f"(ov[nt][0]), "+f"(ov[nt][1]), "+f"(ov[nt][2]), "+f"(ov[nt][3])
                : "r"(a0), "r"(a1), "r"(a2), "r"(a3), "r"(b0), "r"(b1));
        }
    }

    const bool v0 = i0 < NTOK, v1 = i1 < NTOK;
#pragma unroll
    for (int nt = 0; nt < 4; nt++) {
        const int col = h * 32 + nt * 8 + 2 * t;
        if (v0) {
            *(__half2*)(out + ((size_t)b * NTOK + i0) * CDIM + col) =
                __floats2half2_rn(ov[nt][0] * inv0, ov[nt][1] * inv0);
        }
        if (v1) {
            *(__half2*)(out + ((size_t)b * NTOK + i1) * CDIM + col) =
                __floats2half2_rn(ov[nt][2] * inv1, ov[nt][3] * inv1);
        }
    }
}

// ---------------------------------------------------------------------------
// Pipeline resources: created ONCE, during the (uncaptured) correctness call,
// via magic statics — no CUDA resource creation happens during graph capture.
// ---------------------------------------------------------------------------
struct PipeRes {
    cudaStream_t s1, s2;
    cudaEvent_t  evQ[NCHUNK], evA[NCHUNK], evP;
    PipeRes() {
        cudaStreamCreateWithFlags(&s1, cudaStreamNonBlocking);
        cudaStreamCreateWithFlags(&s2, cudaStreamNonBlocking);
        for (int i = 0; i < NCHUNK; i++) {
            cudaEventCreateWithFlags(&evQ[i], cudaEventDisableTiming);
            cudaEventCreateWithFlags(&evA[i], cudaEventDisableTiming);
        }
        cudaEventCreateWithFlags(&evP, cudaEventDisableTiming);
    }
};
static PipeRes& pipe_res() { static PipeRes p; return p; }

// ---------------------------------------------------------------------------
// Launch: chunked 3-stage pipeline across streams (QKV -> attn -> proj)
// ---------------------------------------------------------------------------
extern "C" void kernel_launch(void* const* d_in, const int* in_sizes, int n_in,
                              void* d_out, int out_size)
{
    const float* x      = (const float*)d_in[0];
    const float* qkv_w  = (const float*)d_in[1];
    const float* qkv_b  = (const float*)d_in[2];
    const float* rpb    = (const float*)d_in[3];
    const float* proj_w = (const float*)d_in[4];
    const float* proj_b = (const float*)d_in[5];
    float* out = (float*)d_out;

    __half* qkvh = nullptr;
    __half* atth = nullptr;
    uint32_t* wqkv = nullptr;
    uint32_t* wproj = nullptr;
    uint32_t* biasT = nullptr;
    cudaGetSymbolAddress((void**)&qkvh, g_qkv);
    cudaGetSymbolAddress((void**)&atth, g_att);
    cudaGetSymbolAddress((void**)&wqkv, g_wqkv);
    cudaGetSymbolAddress((void**)&wproj, g_wproj);
    cudaGetSymbolAddress((void**)&biasT, g_bias);

    constexpr int SMEM = 16384 * 4;   // 64 KB (A fragment image)
    cudaFuncSetAttribute(h16_gemm<float, __half, 768>,
                         cudaFuncAttributeMaxDynamicSharedMemorySize, SMEM);
    cudaFuncSetAttribute(h16_gemm<__half, float, 256>,
                         cudaFuncAttributeMaxDynamicSharedMemorySize, SMEM);

    PipeRes& P = pipe_res();

    // stream 0 (capture origin): one-time conversions
    convert_w<<<384, 256>>>(qkv_w, wqkv, 768);
    convert_w<<<128, 256>>>(proj_w, wproj, 256);
    build_bias<<<64, 256>>>(rpb, biasT);

    // chunked pipeline
    for (int c = 0; c < NCHUNK; c++) {
        // QKV chunk on stream 0
        h16_gemm<float, __half, 768><<<RCH / 128, 256, SMEM>>>(
            x + (size_t)c * RCH * 256, wqkv, qkv_b,
            qkvh + (size_t)c * RCH * 768);
        cudaEventRecord(P.evQ[c], 0);

        // attention chunk on s1
        cudaStreamWaitEvent(P.s1, P.evQ[c], 0);
        {
            dim3 grid(WCH, NHEAD);
            window_attn_h16<<<grid, 128, 0, P.s1>>>(
                qkvh + (size_t)c * RCH * 768, biasT,
                atth + (size_t)c * RCH * 256);
        }
        cudaEventRecord(P.evA[c], P.s1);

        // projection chunk on s2
        cudaStreamWaitEvent(P.s2, P.evA[c], 0);
        h16_gemm<__half, float, 256><<<RCH / 128, 256, SMEM, P.s2>>>(
            atth + (size_t)c * RCH * 256, wproj, proj_b,
            out + (size_t)c * RCH * 256);
    }

    // join all side-stream work back into the capture-origin stream
    cudaEventRecord(P.evP, P.s2);
    cudaStreamWaitEvent(0, P.evP, 0);
}